// round 4
// baseline (speedup 1.0000x reference)
#include <cuda_runtime.h>
#include <cuda_bf16.h>
#include <cstdint>

// Problem constants (fixed by setup_inputs)
#define DIM   128
#define LMAX  60000
#define CMAX  30000
#define EMAX  360000
#define NITER 8

// ---------------- scratch (device globals; no allocations allowed) ----------
__device__ float g_l2c_msg[(size_t)LMAX * DIM];
__device__ float g_c2l_msg[(size_t)CMAX * DIM];
__device__ float g_l2l_msg[(size_t)LMAX * DIM];
__device__ float g_aggr_c [(size_t)CMAX * DIM];
__device__ float g_aggr_l [(size_t)LMAX * DIM];
__device__ float g_gi_c   [(size_t)CMAX * 3 * DIM];
__device__ float g_gh_c   [(size_t)CMAX * 3 * DIM];
__device__ float g_gi_l   [(size_t)LMAX * 3 * DIM];
__device__ float g_gh_l   [(size_t)LMAX * 3 * DIM];
// CSR scratch
__device__ int g_cnt_c[CMAX];
__device__ int g_cnt_l[LMAX];
__device__ int g_off_c[CMAX + 1];
__device__ int g_off_l[LMAX + 1];
__device__ int g_cur_c[CMAX];
__device__ int g_cur_l[LMAX];
__device__ int g_src_c[EMAX];
__device__ int g_src_l[EMAX];
// pre-split bf16 weight planes (u32 = 2 bf16), hi then lo
#define WSPLIT_TOTAL 172032
__device__ uint32_t g_whi[WSPLIT_TOTAL];
__device__ uint32_t g_wlo[WSPLIT_TOTAL];

// ======================= helpers =============================================
__device__ __forceinline__ uint32_t smem_u32(const void* p) {
    uint32_t a;
    asm("{ .reg .u64 t; cvta.to.shared.u64 t, %1; cvt.u32.u64 %0, t; }"
        : "=r"(a) : "l"(p));
    return a;
}

// pack two floats to bf16x2 (lo element = first arg)
__device__ __forceinline__ uint32_t pack_bf16(float lo, float hi) {
    uint32_t r;
    asm("cvt.rn.bf16x2.f32 %0, %1, %2;" : "=r"(r) : "f"(hi), "f"(lo));
    return r;
}

// split pair (x,y) into hi bf16x2 + lo (residual) bf16x2
__device__ __forceinline__ void split2(float x, float y, uint32_t& hi, uint32_t& lo) {
    uint32_t h = pack_bf16(x, y);
    float hx = __uint_as_float(h << 16);
    float hy = __uint_as_float(h & 0xffff0000u);
    hi = h;
    lo = pack_bf16(x - hx, y - hy);
}

__device__ __forceinline__ void cp16(uint32_t dst, const void* src) {
    asm volatile("cp.async.ca.shared.global [%0], [%1], 16;"
                 :: "r"(dst), "l"(src) : "memory");
}
#define CP_COMMIT() asm volatile("cp.async.commit_group;" ::: "memory")
#define CP_WAIT0()  asm volatile("cp.async.wait_group 0;" ::: "memory")
#define CP_WAIT1()  asm volatile("cp.async.wait_group 1;" ::: "memory")

__device__ __forceinline__ void mma_bf16(float* d, const uint32_t* a,
                                         uint32_t b0, uint32_t b1) {
    asm volatile(
        "mma.sync.aligned.m16n8k16.row.col.f32.bf16.bf16.f32 "
        "{%0,%1,%2,%3}, {%4,%5,%6,%7}, {%8,%9}, {%0,%1,%2,%3};"
        : "+f"(d[0]), "+f"(d[1]), "+f"(d[2]), "+f"(d[3])
        : "r"(a[0]), "r"(a[1]), "r"(a[2]), "r"(a[3]), "r"(b0), "r"(b1));
}

// swizzled u32 index within a 128x8 plane: conflict-free fragment reads
#define IDX(r, q) ((((r) << 3)) | ((q) ^ ((r) & 7)))

// ======================= weight pre-split ====================================
// W [rows, 2*kp] fp32 -> hi/lo bf16x2 planes with within-32B row swizzle
__global__ void split_w(const float* __restrict__ W, uint32_t* __restrict__ hi,
                        uint32_t* __restrict__ lo, int total_pairs, int kp)
{
    int i = blockIdx.x * 256 + threadIdx.x;
    if (i >= total_pairs) return;
    int r = i / kp, p = i - r * kp;
    float2 f = ((const float2*)W)[i];
    uint32_t h, l;
    split2(f.x, f.y, h, l);
    int dp = (p & ~7) | ((p & 7) ^ (r & 7));
    hi[(size_t)r * kp + dp] = h;
    lo[(size_t)r * kp + dp] = l;
}

// ======================= MMA chunk primitives ================================
// smem chunk buffer layout (u32): [Ah 1024][Al 1024][Bh 1024][Bl 1024]
__device__ __forceinline__ void mma_chunk(const uint32_t* __restrict__ sb,
                                          float acc[16][4], int lane, int wid)
{
    const uint32_t* Ah = sb;
    const uint32_t* Al = sb + 1024;
    const uint32_t* Bh = sb + 2048;
    const uint32_t* Bl = sb + 3072;
    const int r = wid * 16 + (lane >> 2);
    const int q = lane & 3;
    uint32_t ah[4], al[4];
    ah[0] = Ah[IDX(r, q)];     ah[1] = Ah[IDX(r + 8, q)];
    ah[2] = Ah[IDX(r, q + 4)]; ah[3] = Ah[IDX(r + 8, q + 4)];
    al[0] = Al[IDX(r, q)];     al[1] = Al[IDX(r + 8, q)];
    al[2] = Al[IDX(r, q + 4)]; al[3] = Al[IDX(r + 8, q + 4)];
#pragma unroll
    for (int nt = 0; nt < 16; nt++) {
        const int n = nt * 8 + (lane >> 2);
        uint32_t bh0 = Bh[IDX(n, q)], bh1 = Bh[IDX(n, q + 4)];
        uint32_t bl0 = Bl[IDX(n, q)], bl1 = Bl[IDX(n, q + 4)];
        mma_bf16(acc[nt], ah, bh0, bh1);
        mma_bf16(acc[nt], al, bh0, bh1);
        mma_bf16(acc[nt], ah, bl0, bl1);
    }
}

// stage-2 chunk: A fragments split on the fly from fp32 accumulators
__device__ __forceinline__ void mma_chunk_areg(const uint32_t* __restrict__ sb,
                                               const float a1[16][4], float acc[16][4],
                                               int c, int lane)
{
    const uint32_t* Bh = sb + 2048;
    const uint32_t* Bl = sb + 3072;
    const int q = lane & 3;
    uint32_t ah[4], al[4];
    split2(a1[2 * c][0],     a1[2 * c][1],     ah[0], al[0]);
    split2(a1[2 * c][2],     a1[2 * c][3],     ah[1], al[1]);
    split2(a1[2 * c + 1][0], a1[2 * c + 1][1], ah[2], al[2]);
    split2(a1[2 * c + 1][2], a1[2 * c + 1][3], ah[3], al[3]);
#pragma unroll
    for (int nt = 0; nt < 16; nt++) {
        const int n = nt * 8 + (lane >> 2);
        uint32_t bh0 = Bh[IDX(n, q)], bh1 = Bh[IDX(n, q + 4)];
        uint32_t bl0 = Bl[IDX(n, q)], bl1 = Bl[IDX(n, q + 4)];
        mma_bf16(acc[nt], ah, bh0, bh1);
        mma_bf16(acc[nt], al, bh0, bh1);
        mma_bf16(acc[nt], ah, bl0, bl1);
    }
}

// ======================= generic GEMM ========================================
// out[N, NOtot] (cols n0..n0+127) = act(A @ W^T + bias); A = concat(A0,A1) [N,Ktot]
__global__ __launch_bounds__(256, 2)
void gemm_bf3(const float* __restrict__ A0, const float* __restrict__ A1,
              const uint32_t* __restrict__ Wh, const uint32_t* __restrict__ Wl,
              const float* __restrict__ bias, float* __restrict__ out,
              int N, int NOtot, int Ktot, int relu, int perm)
{
    __shared__ __align__(16) uint32_t sm[2 * 4096];

    const int t = threadIdx.x, lane = t & 31, wid = t >> 5;
    const int m0 = blockIdx.x * 128, n0 = blockIdx.y * 128;
    const int Kp = Ktot >> 1;
    const int nch = Ktot >> 4;

    float acc[16][4];
#pragma unroll
    for (int i = 0; i < 16; i++)
#pragma unroll
        for (int j = 0; j < 4; j++) acc[i][j] = 0.f;

    // A loader mapping
    const int arow_l = t >> 1;
    const int afl = (t & 1) * 8;        // float col offset in chunk
    const int grow = m0 + arow_l;
    int arow = (perm ? (grow ^ 1) : grow);
    if (grow >= N) arow = 0;            // clamp (garbage rows never stored)
    float4 ra0, ra1;

    // W cp.async mapping: row = t&127, plane = t>>7
    const int wrow = t & 127;
    const int wpl = t >> 7;
    const uint32_t* wsrc_base = (wpl ? Wl : Wh) + (size_t)(n0 + wrow) * Kp;

#define LDA(ch) do { \
        const int kc = (ch) << 4; \
        const float* src = (kc < 128) ? A0 : A1; \
        const float* p = src + (size_t)arow * 128 + (kc & 127) + afl; \
        ra0 = *(const float4*)p; ra1 = *(const float4*)(p + 4); \
    } while (0)

#define STA(buf) do { \
        uint32_t* Ah = sm + (buf) * 4096; \
        uint32_t* Al = Ah + 1024; \
        uint32_t h0, l0; \
        split2(ra0.x, ra0.y, h0, l0); Ah[IDX(arow_l, (afl >> 1) + 0)] = h0; Al[IDX(arow_l, (afl >> 1) + 0)] = l0; \
        split2(ra0.z, ra0.w, h0, l0); Ah[IDX(arow_l, (afl >> 1) + 1)] = h0; Al[IDX(arow_l, (afl >> 1) + 1)] = l0; \
        split2(ra1.x, ra1.y, h0, l0); Ah[IDX(arow_l, (afl >> 1) + 2)] = h0; Al[IDX(arow_l, (afl >> 1) + 2)] = l0; \
        split2(ra1.z, ra1.w, h0, l0); Ah[IDX(arow_l, (afl >> 1) + 3)] = h0; Al[IDX(arow_l, (afl >> 1) + 3)] = l0; \
    } while (0)

#define CPW(ch, buf) do { \
        const uint32_t* gp = wsrc_base + ((ch) << 3); \
        uint32_t daddr = smem_u32(sm + (buf) * 4096 + (2 + wpl) * 1024 + wrow * 8); \
        cp16(daddr, gp); cp16(daddr + 16, gp + 4); \
    } while (0)

    LDA(0); CPW(0, 0); CP_COMMIT();
    STA(0);
    if (nch > 1) { LDA(1); CPW(1, 1); CP_COMMIT(); CP_WAIT1(); }
    else CP_WAIT0();
    __syncthreads();

    for (int ch = 0; ch < nch; ch++) {
        mma_chunk(sm + (ch & 1) * 4096, acc, lane, wid);
        __syncthreads();
        if (ch + 1 < nch) {
            STA((ch + 1) & 1);
            if (ch + 2 < nch) { LDA(ch + 2); CPW(ch + 2, ch & 1); CP_COMMIT(); CP_WAIT1(); }
            else CP_WAIT0();
            __syncthreads();
        }
    }

    // epilogue
    const int r0 = m0 + wid * 16 + (lane >> 2);
#pragma unroll
    for (int nt = 0; nt < 16; nt++) {
        const int col = n0 + nt * 8 + 2 * (lane & 3);
        float bx = bias[col], by = bias[col + 1];
        if (r0 < N) {
            float2 o = {acc[nt][0] + bx, acc[nt][1] + by};
            if (relu) { o.x = fmaxf(o.x, 0.f); o.y = fmaxf(o.y, 0.f); }
            *(float2*)(out + (size_t)r0 * NOtot + col) = o;
        }
        if (r0 + 8 < N) {
            float2 o = {acc[nt][2] + bx, acc[nt][3] + by};
            if (relu) { o.x = fmaxf(o.x, 0.f); o.y = fmaxf(o.y, 0.f); }
            *(float2*)(out + (size_t)(r0 + 8) * NOtot + col) = o;
        }
    }
#undef LDA
#undef STA
#undef CPW
}

// ======================= fused 2-layer MLP ===================================
// out = relu(A @ W0^T + b0) @ W1^T + b1 ; all [*,128]x[128,128]
__global__ __launch_bounds__(256, 1)
void mlp2_bf3(const float* __restrict__ A0,
              const uint32_t* __restrict__ W0h, const uint32_t* __restrict__ W0l,
              const float* __restrict__ b0,
              const uint32_t* __restrict__ W1h, const uint32_t* __restrict__ W1l,
              const float* __restrict__ b1,
              float* __restrict__ out, int N, int perm)
{
    __shared__ __align__(16) uint32_t sm[2 * 4096];
    __shared__ float sb0[128];

    const int t = threadIdx.x, lane = t & 31, wid = t >> 5;
    const int m0 = blockIdx.x * 128;

    if (t < 128) sb0[t] = b0[t];

    float acc1[16][4];
#pragma unroll
    for (int i = 0; i < 16; i++)
#pragma unroll
        for (int j = 0; j < 4; j++) acc1[i][j] = 0.f;

    const int arow_l = t >> 1;
    const int afl = (t & 1) * 8;
    const int grow = m0 + arow_l;
    int arow = (perm ? (grow ^ 1) : grow);
    if (grow >= N) arow = 0;
    float4 ra0, ra1;

    const int wrow = t & 127;
    const int wpl = t >> 7;
    const uint32_t* w0_base = (wpl ? W0l : W0h) + (size_t)wrow * 64;
    const uint32_t* w1_base = (wpl ? W1l : W1h) + (size_t)wrow * 64;

#define LDA1(ch) do { \
        const float* p = A0 + (size_t)arow * 128 + ((ch) << 4) + afl; \
        ra0 = *(const float4*)p; ra1 = *(const float4*)(p + 4); \
    } while (0)
#define STA1(buf) do { \
        uint32_t* Ah = sm + (buf) * 4096; \
        uint32_t* Al = Ah + 1024; \
        uint32_t h0, l0; \
        split2(ra0.x, ra0.y, h0, l0); Ah[IDX(arow_l, (afl >> 1) + 0)] = h0; Al[IDX(arow_l, (afl >> 1) + 0)] = l0; \
        split2(ra0.z, ra0.w, h0, l0); Ah[IDX(arow_l, (afl >> 1) + 1)] = h0; Al[IDX(arow_l, (afl >> 1) + 1)] = l0; \
        split2(ra1.x, ra1.y, h0, l0); Ah[IDX(arow_l, (afl >> 1) + 2)] = h0; Al[IDX(arow_l, (afl >> 1) + 2)] = l0; \
        split2(ra1.z, ra1.w, h0, l0); Ah[IDX(arow_l, (afl >> 1) + 3)] = h0; Al[IDX(arow_l, (afl >> 1) + 3)] = l0; \
    } while (0)
#define CPW1(wb, ch, buf) do { \
        const uint32_t* gp = (wb) + ((ch) << 3); \
        uint32_t daddr = smem_u32(sm + (buf) * 4096 + (2 + wpl) * 1024 + wrow * 8); \
        cp16(daddr, gp); cp16(daddr + 16, gp + 4); \
    } while (0)

    // ---- stage 1 ----
    LDA1(0); CPW1(w0_base, 0, 0); CP_COMMIT();
    STA1(0);
    LDA1(1); CPW1(w0_base, 1, 1); CP_COMMIT(); CP_WAIT1();
    __syncthreads();
    for (int ch = 0; ch < 8; ch++) {
        mma_chunk(sm + (ch & 1) * 4096, acc1, lane, wid);
        __syncthreads();
        if (ch + 1 < 8) {
            STA1((ch + 1) & 1);
            if (ch + 2 < 8) { LDA1(ch + 2); CPW1(w0_base, ch + 2, ch & 1); CP_COMMIT(); CP_WAIT1(); }
            else CP_WAIT0();
            __syncthreads();
        }
    }

    // bias + relu in registers
#pragma unroll
    for (int nt = 0; nt < 16; nt++) {
        const int col = nt * 8 + 2 * (lane & 3);
        float bx = sb0[col], by = sb0[col + 1];
        acc1[nt][0] = fmaxf(acc1[nt][0] + bx, 0.f);
        acc1[nt][1] = fmaxf(acc1[nt][1] + by, 0.f);
        acc1[nt][2] = fmaxf(acc1[nt][2] + bx, 0.f);
        acc1[nt][3] = fmaxf(acc1[nt][3] + by, 0.f);
    }

    float acc2[16][4];
#pragma unroll
    for (int i = 0; i < 16; i++)
#pragma unroll
        for (int j = 0; j < 4; j++) acc2[i][j] = 0.f;

    // ---- stage 2: A from registers, W1 via cp.async ----
    CPW1(w1_base, 0, 0); CP_COMMIT();
    CPW1(w1_base, 1, 1); CP_COMMIT(); CP_WAIT1();
    __syncthreads();
    for (int ch = 0; ch < 8; ch++) {
        mma_chunk_areg(sm + (ch & 1) * 4096, acc1, acc2, ch, lane);
        __syncthreads();
        if (ch + 1 < 8) {
            if (ch + 2 < 8) { CPW1(w1_base, ch + 2, ch & 1); CP_COMMIT(); CP_WAIT1(); }
            else CP_WAIT0();
            __syncthreads();
        }
    }

    const int r0 = m0 + wid * 16 + (lane >> 2);
#pragma unroll
    for (int nt = 0; nt < 16; nt++) {
        const int col = nt * 8 + 2 * (lane & 3);
        float bx = b1[col], by = b1[col + 1];
        if (r0 < N)
            *(float2*)(out + (size_t)r0 * 128 + col) =
                make_float2(acc2[nt][0] + bx, acc2[nt][1] + by);
        if (r0 + 8 < N)
            *(float2*)(out + (size_t)(r0 + 8) * 128 + col) =
                make_float2(acc2[nt][2] + bx, acc2[nt][3] + by);
    }
#undef LDA1
#undef STA1
#undef CPW1
}

// ======================= CSR build ===========================================
__global__ void hist2(const int* __restrict__ l_e, const int* __restrict__ c_e,
                      int* __restrict__ cnt_l, int* __restrict__ cnt_c, int E)
{
    int i = blockIdx.x * blockDim.x + threadIdx.x;
    if (i < E) {
        atomicAdd(&cnt_l[l_e[i]], 1);
        atomicAdd(&cnt_c[c_e[i]], 1);
    }
}

__global__ void exscan(const int* __restrict__ cnt, int* __restrict__ off, int n)
{
    __shared__ int part[1024];
    const int t = threadIdx.x;
    const int chunk = (n + 1023) >> 10;
    const int b = t * chunk;
    const int e = min(b + chunk, n);
    int s = 0;
    for (int i = b; i < e; i++) s += cnt[i];
    part[t] = s;
    __syncthreads();
    for (int d = 1; d < 1024; d <<= 1) {
        int v = (t >= d) ? part[t - d] : 0;
        __syncthreads();
        if (t >= d) part[t] += v;
        __syncthreads();
    }
    int run = (t == 0) ? 0 : part[t - 1];
    for (int i = b; i < e; i++) { off[i] = run; run += cnt[i]; }
    if (t == 0) off[n] = part[1023];
}

__global__ void fill2(const int* __restrict__ l_e, const int* __restrict__ c_e,
                      int* __restrict__ cur_l, int* __restrict__ cur_c,
                      int* __restrict__ src_l, int* __restrict__ src_c, int E)
{
    int i = blockIdx.x * blockDim.x + threadIdx.x;
    if (i < E) {
        int l = l_e[i], c = c_e[i];
        src_c[atomicAdd(&cur_c[c], 1)] = l;
        src_l[atomicAdd(&cur_l[l], 1)] = c;
    }
}

// ======================= gather-sum ==========================================
__global__ __launch_bounds__(256)
void gather(const float* __restrict__ msg, const int* __restrict__ off,
            const int* __restrict__ srcs, float* __restrict__ aggr, int n)
{
    int node = blockIdx.x * 8 + (threadIdx.x >> 5);
    if (node >= n) return;
    int lane = threadIdx.x & 31;
    int b = off[node], e = off[node + 1];
    float4 acc = {0.f, 0.f, 0.f, 0.f};
    for (int i = b; i < e; i++) {
        const float4 v = *((const float4*)(msg + (size_t)srcs[i] * DIM) + lane);
        acc.x += v.x; acc.y += v.y; acc.z += v.z; acc.w += v.w;
    }
    *((float4*)(aggr + (size_t)node * DIM) + lane) = acc;
}

// ---------------- GRU elementwise gate math ----------------------------------
__device__ __forceinline__ float sigmoidf_(float x) { return 1.f / (1.f + expf(-x)); }

__global__ void gru_elem(const float* __restrict__ gi, const float* __restrict__ gh,
                         const float* __restrict__ h, float* __restrict__ hnew, int N)
{
    int idx = blockIdx.x * blockDim.x + threadIdx.x;
    if (idx >= N * DIM) return;
    int row = idx >> 7, col = idx & 127;
    const float* gir = gi + (size_t)row * 3 * DIM;
    const float* ghr = gh + (size_t)row * 3 * DIM;
    float ir = gir[col], iz = gir[DIM + col], in_ = gir[2 * DIM + col];
    float hr = ghr[col], hz = ghr[DIM + col], hn  = ghr[2 * DIM + col];
    float r = sigmoidf_(ir + hr);
    float z = sigmoidf_(iz + hz);
    float n = tanhf(in_ + r * hn);
    hnew[idx] = (1.f - z) * n + z * h[idx];
}

// ---------------- launch ------------------------------------------------------
extern "C" void kernel_launch(void* const* d_in, const int* in_sizes, int n_in,
                              void* d_out, int out_size)
{
    const int D = DIM;
    const int E = in_sizes[2];
    const int L = in_sizes[4] / D;
    const int C = in_sizes[5] / D;

    const int*   l_edge = (const int*)d_in[2];
    const int*   c_edge = (const int*)d_in[3];
    const float* l_emb0 = (const float*)d_in[4];
    const float* c_emb0 = (const float*)d_in[5];

    const float* l2c_W0 = (const float*)d_in[6];
    const float* l2c_b0 = (const float*)d_in[7];
    const float* l2c_W1 = (const float*)d_in[8];
    const float* l2c_b1 = (const float*)d_in[9];
    const float* c2l_W0 = (const float*)d_in[10];
    const float* c2l_b0 = (const float*)d_in[11];
    const float* c2l_W1 = (const float*)d_in[12];
    const float* c2l_b1 = (const float*)d_in[13];
    const float* l2l_W0 = (const float*)d_in[14];
    const float* l2l_b0 = (const float*)d_in[15];
    const float* l2l_W1 = (const float*)d_in[16];
    const float* l2l_b1 = (const float*)d_in[17];
    const float* c_Wih  = (const float*)d_in[18];
    const float* c_Whh  = (const float*)d_in[19];
    const float* c_bih  = (const float*)d_in[20];
    const float* c_bhh  = (const float*)d_in[21];
    const float* l_Wih  = (const float*)d_in[22];
    const float* l_Whh  = (const float*)d_in[23];
    const float* l_bih  = (const float*)d_in[24];
    const float* l_bhh  = (const float*)d_in[25];

    float* out   = (float*)d_out;
    float* louts = out;                                // [9, L, D]
    float* couts = out + (size_t)(NITER + 1) * L * D;  // [9, C, D]

    float *l2c_msg, *c2l_msg, *l2l_msg, *aggr_c, *aggr_l, *gi_c, *gh_c, *gi_l, *gh_l;
    cudaGetSymbolAddress((void**)&l2c_msg, g_l2c_msg);
    cudaGetSymbolAddress((void**)&c2l_msg, g_c2l_msg);
    cudaGetSymbolAddress((void**)&l2l_msg, g_l2l_msg);
    cudaGetSymbolAddress((void**)&aggr_c,  g_aggr_c);
    cudaGetSymbolAddress((void**)&aggr_l,  g_aggr_l);
    cudaGetSymbolAddress((void**)&gi_c,    g_gi_c);
    cudaGetSymbolAddress((void**)&gh_c,    g_gh_c);
    cudaGetSymbolAddress((void**)&gi_l,    g_gi_l);
    cudaGetSymbolAddress((void**)&gh_l,    g_gh_l);

    int *cnt_c, *cnt_l, *off_c, *off_l, *cur_c, *cur_l, *src_c, *src_l;
    cudaGetSymbolAddress((void**)&cnt_c, g_cnt_c);
    cudaGetSymbolAddress((void**)&cnt_l, g_cnt_l);
    cudaGetSymbolAddress((void**)&off_c, g_off_c);
    cudaGetSymbolAddress((void**)&off_l, g_off_l);
    cudaGetSymbolAddress((void**)&cur_c, g_cur_c);
    cudaGetSymbolAddress((void**)&cur_l, g_cur_l);
    cudaGetSymbolAddress((void**)&src_c, g_src_c);
    cudaGetSymbolAddress((void**)&src_l, g_src_l);

    uint32_t *whi, *wlo;
    cudaGetSymbolAddress((void**)&whi, g_whi);
    cudaGetSymbolAddress((void**)&wlo, g_wlo);

    // plane offsets (u32 pairs): 6 MLP weights (8192 each), c_Wih/c_Whh (24576),
    // l_Wih (49152), l_Whh (24576)
    const int o_l2c0 = 0,      o_l2c1 = 8192,  o_c2l0 = 16384, o_c2l1 = 24576;
    const int o_l2l0 = 32768,  o_l2l1 = 40960;
    const int o_cih  = 49152,  o_chh  = 73728;
    const int o_lih  = 98304,  o_lhh  = 147456;

    // ---- pre-split weights into bf16 hi/lo planes ----
    split_w<<<32, 256>>>(l2c_W0, whi + o_l2c0, wlo + o_l2c0, 8192, 64);
    split_w<<<32, 256>>>(l2c_W1, whi + o_l2c1, wlo + o_l2c1, 8192, 64);
    split_w<<<32, 256>>>(c2l_W0, whi + o_c2l0, wlo + o_c2l0, 8192, 64);
    split_w<<<32, 256>>>(c2l_W1, whi + o_c2l1, wlo + o_c2l1, 8192, 64);
    split_w<<<32, 256>>>(l2l_W0, whi + o_l2l0, wlo + o_l2l0, 8192, 64);
    split_w<<<32, 256>>>(l2l_W1, whi + o_l2l1, wlo + o_l2l1, 8192, 64);
    split_w<<<96, 256>>>(c_Wih,  whi + o_cih,  wlo + o_cih,  24576, 64);
    split_w<<<96, 256>>>(c_Whh,  whi + o_chh,  wlo + o_chh,  24576, 64);
    split_w<<<192, 256>>>(l_Wih, whi + o_lih,  wlo + o_lih,  49152, 128);
    split_w<<<96, 256>>>(l_Whh,  whi + o_lhh,  wlo + o_lhh,  24576, 64);

    // ---- CSR build (edge structure static across iterations) ----
    cudaMemsetAsync(cnt_c, 0, (size_t)C * sizeof(int));
    cudaMemsetAsync(cnt_l, 0, (size_t)L * sizeof(int));
    hist2<<<(E + 255) / 256, 256>>>(l_edge, c_edge, cnt_l, cnt_c, E);
    exscan<<<1, 1024>>>(cnt_c, off_c, C);
    exscan<<<1, 1024>>>(cnt_l, off_l, L);
    cudaMemcpyAsync(cur_c, off_c, (size_t)C * sizeof(int), cudaMemcpyDeviceToDevice);
    cudaMemcpyAsync(cur_l, off_l, (size_t)L * sizeof(int), cudaMemcpyDeviceToDevice);
    fill2<<<(E + 255) / 256, 256>>>(l_edge, c_edge, cur_l, cur_c, src_l, src_c, E);

    // iteration-0 slices = inputs
    cudaMemcpyAsync(louts, l_emb0, (size_t)L * D * sizeof(float), cudaMemcpyDeviceToDevice);
    cudaMemcpyAsync(couts, c_emb0, (size_t)C * D * sizeof(float), cudaMemcpyDeviceToDevice);

    const int gLx = (L + 127) / 128;
    const int gCx = (C + 127) / 128;
    const dim3 gC3(gCx, 3), gL3(gLx, 3);

    for (int it = 0; it < NITER; it++) {
        const float* l_prev = louts + (size_t)it * L * D;
        const float* c_prev = couts + (size_t)it * C * D;
        float* l_next = louts + (size_t)(it + 1) * L * D;
        float* c_next = couts + (size_t)(it + 1) * C * D;

        // message MLPs (fused 2-layer)
        mlp2_bf3<<<gLx, 256>>>(l_prev, whi + o_l2c0, wlo + o_l2c0, l2c_b0,
                               whi + o_l2c1, wlo + o_l2c1, l2c_b1, l2c_msg, L, 0);
        mlp2_bf3<<<gCx, 256>>>(c_prev, whi + o_c2l0, wlo + o_c2l0, c2l_b0,
                               whi + o_c2l1, wlo + o_c2l1, c2l_b1, c2l_msg, C, 0);
        mlp2_bf3<<<gLx, 256>>>(l_prev, whi + o_l2l0, wlo + o_l2l0, l2l_b0,
                               whi + o_l2l1, wlo + o_l2l1, l2l_b1, l2l_msg, L, 1);

        // clause side
        gather<<<(C + 7) / 8, 256>>>(l2c_msg, off_c, src_c, aggr_c, C);
        gemm_bf3<<<gC3, 256>>>(aggr_c, nullptr, whi + o_cih, wlo + o_cih,
                               c_bih, gi_c, C, 384, 128, 0, 0);
        gemm_bf3<<<gC3, 256>>>(c_prev, nullptr, whi + o_chh, wlo + o_chh,
                               c_bhh, gh_c, C, 384, 128, 0, 0);
        gru_elem<<<(C * D + 255) / 256, 256>>>(gi_c, gh_c, c_prev, c_next, C);

        // literal side
        gather<<<(L + 7) / 8, 256>>>(c2l_msg, off_l, src_l, aggr_l, L);
        gemm_bf3<<<gL3, 256>>>(aggr_l, l2l_msg, whi + o_lih, wlo + o_lih,
                               l_bih, gi_l, L, 384, 256, 0, 0);
        gemm_bf3<<<gL3, 256>>>(l_prev, nullptr, whi + o_lhh, wlo + o_lhh,
                               l_bhh, gh_l, L, 384, 128, 0, 0);
        gru_elem<<<(L * D + 255) / 256, 256>>>(gi_l, gh_l, l_prev, l_next, L);
    }
}

// round 5
// speedup vs baseline: 1.3783x; 1.3783x over previous
#include <cuda_runtime.h>
#include <cuda_bf16.h>
#include <cstdint>

// Problem constants (fixed by setup_inputs)
#define DIM   128
#define LMAX  60000
#define CMAX  30000
#define EMAX  360000
#define NITER 8

// ---------------- scratch (device globals; no allocations allowed) ----------
__device__ float g_l2c_msg[(size_t)LMAX * DIM];
__device__ float g_c2l_msg[(size_t)CMAX * DIM];
__device__ float g_l2l_msg[(size_t)LMAX * DIM];
__device__ float g_aggr_c [(size_t)CMAX * DIM];
__device__ float g_aggr_l [(size_t)LMAX * DIM];
__device__ float g_gi_c   [(size_t)CMAX * 3 * DIM];
__device__ float g_gh_c   [(size_t)CMAX * 3 * DIM];
__device__ float g_gi_l   [(size_t)LMAX * 3 * DIM];
__device__ float g_gh_l   [(size_t)LMAX * 3 * DIM];
// CSR scratch
__device__ int g_cnt_c[CMAX];
__device__ int g_cnt_l[LMAX];
__device__ int g_off_c[CMAX + 1];
__device__ int g_off_l[LMAX + 1];
__device__ int g_cur_c[CMAX];
__device__ int g_cur_l[LMAX];
__device__ int g_src_c[EMAX];
__device__ int g_src_l[EMAX];
// pre-split bf16 weight planes (u32 = 2 bf16), fragment-ordered
#define WSPLIT_TOTAL 172032
__device__ uint32_t g_whi[WSPLIT_TOTAL];
__device__ uint32_t g_wlo[WSPLIT_TOTAL];

// ======================= helpers =============================================
__device__ __forceinline__ uint32_t smem_u32(const void* p) {
    uint32_t a;
    asm("{ .reg .u64 t; cvta.to.shared.u64 t, %1; cvt.u32.u64 %0, t; }"
        : "=r"(a) : "l"(p));
    return a;
}

__device__ __forceinline__ uint32_t pack_bf16(float lo, float hi) {
    uint32_t r;
    asm("cvt.rn.bf16x2.f32 %0, %1, %2;" : "=r"(r) : "f"(hi), "f"(lo));
    return r;
}

__device__ __forceinline__ void split2(float x, float y, uint32_t& hi, uint32_t& lo) {
    uint32_t h = pack_bf16(x, y);
    float hx = __uint_as_float(h << 16);
    float hy = __uint_as_float(h & 0xffff0000u);
    hi = h;
    lo = pack_bf16(x - hx, y - hy);
}

__device__ __forceinline__ void cp16(uint32_t dst, const void* src) {
    asm volatile("cp.async.ca.shared.global [%0], [%1], 16;"
                 :: "r"(dst), "l"(src) : "memory");
}
#define CP_COMMIT() asm volatile("cp.async.commit_group;" ::: "memory")
#define CP_WAIT0()  asm volatile("cp.async.wait_group 0;" ::: "memory")
#define CP_WAIT1()  asm volatile("cp.async.wait_group 1;" ::: "memory")

__device__ __forceinline__ void mma_bf16(float* d, const uint32_t* a,
                                         uint32_t b0, uint32_t b1) {
    asm volatile(
        "mma.sync.aligned.m16n8k16.row.col.f32.bf16.bf16.f32 "
        "{%0,%1,%2,%3}, {%4,%5,%6,%7}, {%8,%9}, {%0,%1,%2,%3};"
        : "+f"(d[0]), "+f"(d[1]), "+f"(d[2]), "+f"(d[3])
        : "r"(a[0]), "r"(a[1]), "r"(a[2]), "r"(a[3]), "r"(b0), "r"(b1));
}

// A-plane swizzled u32 index (128 rows x 8 u32), conflict-free fragment reads
#define IDX(r, q) ((((r) << 3)) | ((q) ^ ((r) & 7)))

// ======================= weight pre-split (fragment-ordered) =================
// For each 128-row n-group and K16 chunk: 1024 u32 per plane laid out so that
// consumer lane reads its 32 u32 via 8 LDS.128 at lane*32 + ((nt/2)^(lane&7))*4.
__global__ void split_w(const float* __restrict__ W, uint32_t* __restrict__ hi,
                        uint32_t* __restrict__ lo, int total_pairs, int kp)
{
    int i = blockIdx.x * 256 + threadIdx.x;
    if (i >= total_pairs) return;
    int R = i / kp, p = i - R * kp;
    float2 f = ((const float2*)W)[i];
    uint32_t h, l;
    split2(f.x, f.y, h, l);
    int ngroup = R >> 7, n = R & 127;
    int ch = p >> 3, q = p & 7;
    int nt = n >> 3, l4 = n & 7;
    int region = l4 * 4 + (q & 3);
    int idx = region * 32 + (((nt >> 1) ^ (region & 7)) << 2) + ((nt & 1) << 1) + (q >> 2);
    size_t base = ((size_t)(ngroup * (kp >> 3) + ch)) << 10;
    hi[base + idx] = h;
    lo[base + idx] = l;
}

// ======================= MMA chunk primitives ================================
// buffer layout (u32): [Ah 1024][Al 1024][Bh 1024][Bl 1024] = 16KB
__device__ __forceinline__ void mma_chunk_v(const uint32_t* __restrict__ sb,
                                            float acc[16][4], int lane, int wid)
{
    const uint32_t* Ah = sb;
    const uint32_t* Al = sb + 1024;
    const int r = wid * 16 + (lane >> 2);
    const int q = lane & 3;
    uint32_t ah[4], al[4];
    ah[0] = Ah[IDX(r, q)];     ah[1] = Ah[IDX(r + 8, q)];
    ah[2] = Ah[IDX(r, q + 4)]; ah[3] = Ah[IDX(r + 8, q + 4)];
    al[0] = Al[IDX(r, q)];     al[1] = Al[IDX(r + 8, q)];
    al[2] = Al[IDX(r, q + 4)]; al[3] = Al[IDX(r + 8, q + 4)];
    const uint32_t* Bh = sb + 2048 + lane * 32;
    const uint32_t* Bl = Bh + 1024;
#pragma unroll
    for (int c = 0; c < 8; c++) {
        const int sw = ((c ^ (lane & 7)) << 2);
        uint4 vh = *(const uint4*)(Bh + sw);
        uint4 vl = *(const uint4*)(Bl + sw);
        mma_bf16(acc[2 * c],     ah, vh.x, vh.y);
        mma_bf16(acc[2 * c],     al, vh.x, vh.y);
        mma_bf16(acc[2 * c],     ah, vl.x, vl.y);
        mma_bf16(acc[2 * c + 1], ah, vh.z, vh.w);
        mma_bf16(acc[2 * c + 1], al, vh.z, vh.w);
        mma_bf16(acc[2 * c + 1], ah, vl.z, vl.w);
    }
}

// stage-2 chunk: A fragments split on the fly from fp32 accumulators
__device__ __forceinline__ void mma_chunk_areg_v(const uint32_t* __restrict__ sb,
                                                 const float a1[16][4], float acc[16][4],
                                                 int c2, int lane)
{
    uint32_t ah[4], al[4];
    split2(a1[2 * c2][0],     a1[2 * c2][1],     ah[0], al[0]);
    split2(a1[2 * c2][2],     a1[2 * c2][3],     ah[1], al[1]);
    split2(a1[2 * c2 + 1][0], a1[2 * c2 + 1][1], ah[2], al[2]);
    split2(a1[2 * c2 + 1][2], a1[2 * c2 + 1][3], ah[3], al[3]);
    const uint32_t* Bh = sb + 2048 + lane * 32;
    const uint32_t* Bl = Bh + 1024;
#pragma unroll
    for (int c = 0; c < 8; c++) {
        const int sw = ((c ^ (lane & 7)) << 2);
        uint4 vh = *(const uint4*)(Bh + sw);
        uint4 vl = *(const uint4*)(Bl + sw);
        mma_bf16(acc[2 * c],     ah, vh.x, vh.y);
        mma_bf16(acc[2 * c],     al, vh.x, vh.y);
        mma_bf16(acc[2 * c],     ah, vl.x, vl.y);
        mma_bf16(acc[2 * c + 1], ah, vh.z, vh.w);
        mma_bf16(acc[2 * c + 1], al, vh.z, vh.w);
        mma_bf16(acc[2 * c + 1], ah, vl.z, vl.w);
    }
}

// ======================= generic GEMM ========================================
// out[N, NOtot] (cols n0..n0+127, n0 = blockIdx.y*128) = act(A @ W^T + bias)
// A = concat(A0, A1) [N, Ktot]; W planes fragment-ordered by split_w.
__global__ __launch_bounds__(256, 2)
void gemm_bf3(const float* __restrict__ A0, const float* __restrict__ A1,
              const uint32_t* __restrict__ Wh, const uint32_t* __restrict__ Wl,
              const float* __restrict__ bias, float* __restrict__ out,
              int N, int NOtot, int Ktot, int relu, int perm)
{
    __shared__ __align__(16) uint32_t sm[3 * 4096];   // 48 KB, triple-buffered

    const int t = threadIdx.x, lane = t & 31, wid = t >> 5;
    const int m0 = blockIdx.x * 128;
    const int nch = Ktot >> 4;

    float acc[16][4];
#pragma unroll
    for (int i = 0; i < 16; i++)
#pragma unroll
        for (int j = 0; j < 4; j++) acc[i][j] = 0.f;

    // A loader mapping
    const int arow_l = t >> 1;
    const int afl = (t & 1) * 8;
    const int grow = m0 + arow_l;
    int arow = (perm ? (grow ^ 1) : grow);
    if (grow >= N) arow = 0;
    float4 ra0, ra1;

    // W cp.async mapping
    const int wrow = t & 127;
    const int wpl = t >> 7;
    const uint32_t* wplane = wpl ? Wl : Wh;
    const size_t wgrp = (size_t)blockIdx.y * nch;

#define LDA(ch) do { \
        const int kc = (ch) << 4; \
        const float* src = (kc < 128) ? A0 : A1; \
        const float* p = src + (size_t)arow * 128 + (kc & 127) + afl; \
        ra0 = *(const float4*)p; ra1 = *(const float4*)(p + 4); \
    } while (0)

#define STA(buf) do { \
        uint32_t* Ah = sm + (buf) * 4096; \
        uint32_t* Al = Ah + 1024; \
        uint32_t h0, l0; \
        split2(ra0.x, ra0.y, h0, l0); Ah[IDX(arow_l, (afl >> 1) + 0)] = h0; Al[IDX(arow_l, (afl >> 1) + 0)] = l0; \
        split2(ra0.z, ra0.w, h0, l0); Ah[IDX(arow_l, (afl >> 1) + 1)] = h0; Al[IDX(arow_l, (afl >> 1) + 1)] = l0; \
        split2(ra1.x, ra1.y, h0, l0); Ah[IDX(arow_l, (afl >> 1) + 2)] = h0; Al[IDX(arow_l, (afl >> 1) + 2)] = l0; \
        split2(ra1.z, ra1.w, h0, l0); Ah[IDX(arow_l, (afl >> 1) + 3)] = h0; Al[IDX(arow_l, (afl >> 1) + 3)] = l0; \
    } while (0)

#define CPW(ch, buf) do { \
        const uint32_t* gp = wplane + ((wgrp + (ch)) << 10) + wrow * 8; \
        uint32_t daddr = smem_u32(sm + (buf) * 4096 + (2 + wpl) * 1024 + wrow * 8); \
        cp16(daddr, gp); cp16(daddr + 16, gp + 4); \
    } while (0)

    // prologue: stage chunks 0 and 1
    LDA(0); CPW(0, 0); CP_COMMIT(); STA(0);
    if (nch > 1) { LDA(1); CPW(1, 1); CP_COMMIT(); STA(1); CP_WAIT1(); }
    else CP_WAIT0();
    __syncthreads();

    for (int ch = 0; ch < nch; ch++) {
        mma_chunk_v(sm + (ch % 3) * 4096, acc, lane, wid);
        if (ch + 1 < nch) {
            if (ch + 2 < nch) {
                LDA(ch + 2); CPW(ch + 2, (ch + 2) % 3); CP_COMMIT();
                STA((ch + 2) % 3);
                CP_WAIT1();
            } else CP_WAIT0();
            __syncthreads();
        }
    }

    // epilogue
    const int n0 = blockIdx.y * 128;
    const int r0 = m0 + wid * 16 + (lane >> 2);
#pragma unroll
    for (int nt = 0; nt < 16; nt++) {
        const int col = n0 + nt * 8 + 2 * (lane & 3);
        float bx = bias[col], by = bias[col + 1];
        if (r0 < N) {
            float2 o = {acc[nt][0] + bx, acc[nt][1] + by};
            if (relu) { o.x = fmaxf(o.x, 0.f); o.y = fmaxf(o.y, 0.f); }
            *(float2*)(out + (size_t)r0 * NOtot + col) = o;
        }
        if (r0 + 8 < N) {
            float2 o = {acc[nt][2] + bx, acc[nt][3] + by};
            if (relu) { o.x = fmaxf(o.x, 0.f); o.y = fmaxf(o.y, 0.f); }
            *(float2*)(out + (size_t)(r0 + 8) * NOtot + col) = o;
        }
    }
#undef LDA
#undef STA
#undef CPW
}

// ======================= fused 2-layer MLP ===================================
// out = relu(A @ W0^T + b0) @ W1^T + b1 ; all [*,128]x[128,128]
__global__ __launch_bounds__(256, 1)
void mlp2_bf3(const float* __restrict__ A0,
              const uint32_t* __restrict__ W0h, const uint32_t* __restrict__ W0l,
              const float* __restrict__ b0,
              const uint32_t* __restrict__ W1h, const uint32_t* __restrict__ W1l,
              const float* __restrict__ b1,
              float* __restrict__ out, int N, int perm)
{
    __shared__ __align__(16) uint32_t sm[3 * 4096];
    __shared__ float sb0[128];

    const int t = threadIdx.x, lane = t & 31, wid = t >> 5;
    const int m0 = blockIdx.x * 128;

    if (t < 128) sb0[t] = b0[t];

    float acc1[16][4];
#pragma unroll
    for (int i = 0; i < 16; i++)
#pragma unroll
        for (int j = 0; j < 4; j++) acc1[i][j] = 0.f;

    const int arow_l = t >> 1;
    const int afl = (t & 1) * 8;
    const int grow = m0 + arow_l;
    int arow = (perm ? (grow ^ 1) : grow);
    if (grow >= N) arow = 0;
    float4 ra0, ra1;

    const int wrow = t & 127;
    const int wpl = t >> 7;
    const uint32_t* w0p = wpl ? W0l : W0h;
    const uint32_t* w1p = wpl ? W1l : W1h;

#define LDA1(ch) do { \
        const float* p = A0 + (size_t)arow * 128 + ((ch) << 4) + afl; \
        ra0 = *(const float4*)p; ra1 = *(const float4*)(p + 4); \
    } while (0)
#define STA1(buf) do { \
        uint32_t* Ah = sm + (buf) * 4096; \
        uint32_t* Al = Ah + 1024; \
        uint32_t h0, l0; \
        split2(ra0.x, ra0.y, h0, l0); Ah[IDX(arow_l, (afl >> 1) + 0)] = h0; Al[IDX(arow_l, (afl >> 1) + 0)] = l0; \
        split2(ra0.z, ra0.w, h0, l0); Ah[IDX(arow_l, (afl >> 1) + 1)] = h0; Al[IDX(arow_l, (afl >> 1) + 1)] = l0; \
        split2(ra1.x, ra1.y, h0, l0); Ah[IDX(arow_l, (afl >> 1) + 2)] = h0; Al[IDX(arow_l, (afl >> 1) + 2)] = l0; \
        split2(ra1.z, ra1.w, h0, l0); Ah[IDX(arow_l, (afl >> 1) + 3)] = h0; Al[IDX(arow_l, (afl >> 1) + 3)] = l0; \
    } while (0)
#define CPW1(wb, ch, buf) do { \
        const uint32_t* gp = (wb) + ((size_t)(ch) << 10) + wrow * 8; \
        uint32_t daddr = smem_u32(sm + (buf) * 4096 + (2 + wpl) * 1024 + wrow * 8); \
        cp16(daddr, gp); cp16(daddr + 16, gp + 4); \
    } while (0)

    // ---- stage 1 ----
    LDA1(0); CPW1(w0p, 0, 0); CP_COMMIT(); STA1(0);
    LDA1(1); CPW1(w0p, 1, 1); CP_COMMIT(); STA1(1); CP_WAIT1();
    __syncthreads();
    for (int ch = 0; ch < 8; ch++) {
        mma_chunk_v(sm + (ch % 3) * 4096, acc1, lane, wid);
        if (ch + 1 < 8) {
            if (ch + 2 < 8) {
                LDA1(ch + 2); CPW1(w0p, ch + 2, (ch + 2) % 3); CP_COMMIT();
                STA1((ch + 2) % 3);
                CP_WAIT1();
            } else CP_WAIT0();
            __syncthreads();
        }
    }
    __syncthreads();   // all warps done with stage-1 buffers

    // bias + relu in registers
#pragma unroll
    for (int nt = 0; nt < 16; nt++) {
        const int col = nt * 8 + 2 * (lane & 3);
        float bx = sb0[col], by = sb0[col + 1];
        acc1[nt][0] = fmaxf(acc1[nt][0] + bx, 0.f);
        acc1[nt][1] = fmaxf(acc1[nt][1] + by, 0.f);
        acc1[nt][2] = fmaxf(acc1[nt][2] + bx, 0.f);
        acc1[nt][3] = fmaxf(acc1[nt][3] + by, 0.f);
    }

    float acc2[16][4];
#pragma unroll
    for (int i = 0; i < 16; i++)
#pragma unroll
        for (int j = 0; j < 4; j++) acc2[i][j] = 0.f;

    // ---- stage 2: A from registers, W1 via cp.async ----
    CPW1(w1p, 0, 0); CP_COMMIT();
    CPW1(w1p, 1, 1); CP_COMMIT(); CP_WAIT1();
    __syncthreads();
    for (int ch = 0; ch < 8; ch++) {
        mma_chunk_areg_v(sm + (ch % 3) * 4096, acc1, acc2, ch, lane);
        if (ch + 1 < 8) {
            if (ch + 2 < 8) { CPW1(w1p, ch + 2, (ch + 2) % 3); CP_COMMIT(); CP_WAIT1(); }
            else CP_WAIT0();
            __syncthreads();
        }
    }

    const int r0 = m0 + wid * 16 + (lane >> 2);
#pragma unroll
    for (int nt = 0; nt < 16; nt++) {
        const int col = nt * 8 + 2 * (lane & 3);
        float bx = b1[col], by = b1[col + 1];
        if (r0 < N)
            *(float2*)(out + (size_t)r0 * 128 + col) =
                make_float2(acc2[nt][0] + bx, acc2[nt][1] + by);
        if (r0 + 8 < N)
            *(float2*)(out + (size_t)(r0 + 8) * 128 + col) =
                make_float2(acc2[nt][2] + bx, acc2[nt][3] + by);
    }
#undef LDA1
#undef STA1
#undef CPW1
}

// ======================= CSR build ===========================================
__global__ void hist2(const int* __restrict__ l_e, const int* __restrict__ c_e,
                      int* __restrict__ cnt_l, int* __restrict__ cnt_c, int E)
{
    int i = blockIdx.x * blockDim.x + threadIdx.x;
    if (i < E) {
        atomicAdd(&cnt_l[l_e[i]], 1);
        atomicAdd(&cnt_c[c_e[i]], 1);
    }
}

__global__ void exscan(const int* __restrict__ cnt, int* __restrict__ off, int n)
{
    __shared__ int part[1024];
    const int t = threadIdx.x;
    const int chunk = (n + 1023) >> 10;
    const int b = t * chunk;
    const int e = min(b + chunk, n);
    int s = 0;
    for (int i = b; i < e; i++) s += cnt[i];
    part[t] = s;
    __syncthreads();
    for (int d = 1; d < 1024; d <<= 1) {
        int v = (t >= d) ? part[t - d] : 0;
        __syncthreads();
        if (t >= d) part[t] += v;
        __syncthreads();
    }
    int run = (t == 0) ? 0 : part[t - 1];
    for (int i = b; i < e; i++) { off[i] = run; run += cnt[i]; }
    if (t == 0) off[n] = part[1023];
}

__global__ void fill2(const int* __restrict__ l_e, const int* __restrict__ c_e,
                      int* __restrict__ cur_l, int* __restrict__ cur_c,
                      int* __restrict__ src_l, int* __restrict__ src_c, int E)
{
    int i = blockIdx.x * blockDim.x + threadIdx.x;
    if (i < E) {
        int l = l_e[i], c = c_e[i];
        src_c[atomicAdd(&cur_c[c], 1)] = l;
        src_l[atomicAdd(&cur_l[l], 1)] = c;
    }
}

// ======================= gather-sum ==========================================
__global__ __launch_bounds__(256)
void gather(const float* __restrict__ msg, const int* __restrict__ off,
            const int* __restrict__ srcs, float* __restrict__ aggr, int n)
{
    int node = blockIdx.x * 8 + (threadIdx.x >> 5);
    if (node >= n) return;
    int lane = threadIdx.x & 31;
    int b = off[node], e = off[node + 1];
    float4 acc = {0.f, 0.f, 0.f, 0.f};
    for (int i = b; i < e; i++) {
        const float4 v = *((const float4*)(msg + (size_t)srcs[i] * DIM) + lane);
        acc.x += v.x; acc.y += v.y; acc.z += v.z; acc.w += v.w;
    }
    *((float4*)(aggr + (size_t)node * DIM) + lane) = acc;
}

// ---------------- GRU elementwise gate math ----------------------------------
__device__ __forceinline__ float fsigmoid(float x) { return 1.f / (1.f + __expf(-x)); }
__device__ __forceinline__ float ftanh(float x) {
    float t = __expf(2.f * fabsf(x));
    float r = 1.f - 2.f / (t + 1.f);
    return copysignf(r, x);
}

__global__ void gru_elem(const float* __restrict__ gi, const float* __restrict__ gh,
                         const float* __restrict__ h, float* __restrict__ hnew, int N)
{
    int idx = blockIdx.x * blockDim.x + threadIdx.x;
    if (idx >= N * DIM) return;
    int row = idx >> 7, col = idx & 127;
    const float* gir = gi + (size_t)row * 3 * DIM;
    const float* ghr = gh + (size_t)row * 3 * DIM;
    float ir = gir[col], iz = gir[DIM + col], in_ = gir[2 * DIM + col];
    float hr = ghr[col], hz = ghr[DIM + col], hn  = ghr[2 * DIM + col];
    float r = fsigmoid(ir + hr);
    float z = fsigmoid(iz + hz);
    float n = ftanh(in_ + r * hn);
    hnew[idx] = (1.f - z) * n + z * h[idx];
}

// ---------------- launch ------------------------------------------------------
extern "C" void kernel_launch(void* const* d_in, const int* in_sizes, int n_in,
                              void* d_out, int out_size)
{
    const int D = DIM;
    const int E = in_sizes[2];
    const int L = in_sizes[4] / D;
    const int C = in_sizes[5] / D;

    const int*   l_edge = (const int*)d_in[2];
    const int*   c_edge = (const int*)d_in[3];
    const float* l_emb0 = (const float*)d_in[4];
    const float* c_emb0 = (const float*)d_in[5];

    const float* l2c_W0 = (const float*)d_in[6];
    const float* l2c_b0 = (const float*)d_in[7];
    const float* l2c_W1 = (const float*)d_in[8];
    const float* l2c_b1 = (const float*)d_in[9];
    const float* c2l_W0 = (const float*)d_in[10];
    const float* c2l_b0 = (const float*)d_in[11];
    const float* c2l_W1 = (const float*)d_in[12];
    const float* c2l_b1 = (const float*)d_in[13];
    const float* l2l_W0 = (const float*)d_in[14];
    const float* l2l_b0 = (const float*)d_in[15];
    const float* l2l_W1 = (const float*)d_in[16];
    const float* l2l_b1 = (const float*)d_in[17];
    const float* c_Wih  = (const float*)d_in[18];
    const float* c_Whh  = (const float*)d_in[19];
    const float* c_bih  = (const float*)d_in[20];
    const float* c_bhh  = (const float*)d_in[21];
    const float* l_Wih  = (const float*)d_in[22];
    const float* l_Whh  = (const float*)d_in[23];
    const float* l_bih  = (const float*)d_in[24];
    const float* l_bhh  = (const float*)d_in[25];

    float* out   = (float*)d_out;
    float* louts = out;                                // [9, L, D]
    float* couts = out + (size_t)(NITER + 1) * L * D;  // [9, C, D]

    float *l2c_msg, *c2l_msg, *l2l_msg, *aggr_c, *aggr_l, *gi_c, *gh_c, *gi_l, *gh_l;
    cudaGetSymbolAddress((void**)&l2c_msg, g_l2c_msg);
    cudaGetSymbolAddress((void**)&c2l_msg, g_c2l_msg);
    cudaGetSymbolAddress((void**)&l2l_msg, g_l2l_msg);
    cudaGetSymbolAddress((void**)&aggr_c,  g_aggr_c);
    cudaGetSymbolAddress((void**)&aggr_l,  g_aggr_l);
    cudaGetSymbolAddress((void**)&gi_c,    g_gi_c);
    cudaGetSymbolAddress((void**)&gh_c,    g_gh_c);
    cudaGetSymbolAddress((void**)&gi_l,    g_gi_l);
    cudaGetSymbolAddress((void**)&gh_l,    g_gh_l);

    int *cnt_c, *cnt_l, *off_c, *off_l, *cur_c, *cur_l, *src_c, *src_l;
    cudaGetSymbolAddress((void**)&cnt_c, g_cnt_c);
    cudaGetSymbolAddress((void**)&cnt_l, g_cnt_l);
    cudaGetSymbolAddress((void**)&off_c, g_off_c);
    cudaGetSymbolAddress((void**)&off_l, g_off_l);
    cudaGetSymbolAddress((void**)&cur_c, g_cur_c);
    cudaGetSymbolAddress((void**)&cur_l, g_cur_l);
    cudaGetSymbolAddress((void**)&src_c, g_src_c);
    cudaGetSymbolAddress((void**)&src_l, g_src_l);

    uint32_t *whi, *wlo;
    cudaGetSymbolAddress((void**)&whi, g_whi);
    cudaGetSymbolAddress((void**)&wlo, g_wlo);

    const int o_l2c0 = 0,      o_l2c1 = 8192,  o_c2l0 = 16384, o_c2l1 = 24576;
    const int o_l2l0 = 32768,  o_l2l1 = 40960;
    const int o_cih  = 49152,  o_chh  = 73728;
    const int o_lih  = 98304,  o_lhh  = 147456;

    // ---- pre-split weights into fragment-ordered bf16 hi/lo planes ----
    split_w<<<32, 256>>>(l2c_W0, whi + o_l2c0, wlo + o_l2c0, 8192, 64);
    split_w<<<32, 256>>>(l2c_W1, whi + o_l2c1, wlo + o_l2c1, 8192, 64);
    split_w<<<32, 256>>>(c2l_W0, whi + o_c2l0, wlo + o_c2l0, 8192, 64);
    split_w<<<32, 256>>>(c2l_W1, whi + o_c2l1, wlo + o_c2l1, 8192, 64);
    split_w<<<32, 256>>>(l2l_W0, whi + o_l2l0, wlo + o_l2l0, 8192, 64);
    split_w<<<32, 256>>>(l2l_W1, whi + o_l2l1, wlo + o_l2l1, 8192, 64);
    split_w<<<96, 256>>>(c_Wih,  whi + o_cih,  wlo + o_cih,  24576, 64);
    split_w<<<96, 256>>>(c_Whh,  whi + o_chh,  wlo + o_chh,  24576, 64);
    split_w<<<192, 256>>>(l_Wih, whi + o_lih,  wlo + o_lih,  49152, 128);
    split_w<<<96, 256>>>(l_Whh,  whi + o_lhh,  wlo + o_lhh,  24576, 64);

    // ---- CSR build (edge structure static across iterations) ----
    cudaMemsetAsync(cnt_c, 0, (size_t)C * sizeof(int));
    cudaMemsetAsync(cnt_l, 0, (size_t)L * sizeof(int));
    hist2<<<(E + 255) / 256, 256>>>(l_edge, c_edge, cnt_l, cnt_c, E);
    exscan<<<1, 1024>>>(cnt_c, off_c, C);
    exscan<<<1, 1024>>>(cnt_l, off_l, L);
    cudaMemcpyAsync(cur_c, off_c, (size_t)C * sizeof(int), cudaMemcpyDeviceToDevice);
    cudaMemcpyAsync(cur_l, off_l, (size_t)L * sizeof(int), cudaMemcpyDeviceToDevice);
    fill2<<<(E + 255) / 256, 256>>>(l_edge, c_edge, cur_l, cur_c, src_l, src_c, E);

    // iteration-0 slices = inputs
    cudaMemcpyAsync(louts, l_emb0, (size_t)L * D * sizeof(float), cudaMemcpyDeviceToDevice);
    cudaMemcpyAsync(couts, c_emb0, (size_t)C * D * sizeof(float), cudaMemcpyDeviceToDevice);

    const int gLx = (L + 127) / 128;
    const int gCx = (C + 127) / 128;
    const dim3 gC3(gCx, 3), gL3(gLx, 3);

    for (int it = 0; it < NITER; it++) {
        const float* l_prev = louts + (size_t)it * L * D;
        const float* c_prev = couts + (size_t)it * C * D;
        float* l_next = louts + (size_t)(it + 1) * L * D;
        float* c_next = couts + (size_t)(it + 1) * C * D;

        // message MLPs (fused 2-layer)
        mlp2_bf3<<<gLx, 256>>>(l_prev, whi + o_l2c0, wlo + o_l2c0, l2c_b0,
                               whi + o_l2c1, wlo + o_l2c1, l2c_b1, l2c_msg, L, 0);
        mlp2_bf3<<<gCx, 256>>>(c_prev, whi + o_c2l0, wlo + o_c2l0, c2l_b0,
                               whi + o_c2l1, wlo + o_c2l1, c2l_b1, c2l_msg, C, 0);
        mlp2_bf3<<<gLx, 256>>>(l_prev, whi + o_l2l0, wlo + o_l2l0, l2l_b0,
                               whi + o_l2l1, wlo + o_l2l1, l2l_b1, l2l_msg, L, 1);

        // clause side
        gather<<<(C + 7) / 8, 256>>>(l2c_msg, off_c, src_c, aggr_c, C);
        gemm_bf3<<<gC3, 256>>>(aggr_c, nullptr, whi + o_cih, wlo + o_cih,
                               c_bih, gi_c, C, 384, 128, 0, 0);
        gemm_bf3<<<gC3, 256>>>(c_prev, nullptr, whi + o_chh, wlo + o_chh,
                               c_bhh, gh_c, C, 384, 128, 0, 0);
        gru_elem<<<(C * D + 255) / 256, 256>>>(gi_c, gh_c, c_prev, c_next, C);

        // literal side
        gather<<<(L + 7) / 8, 256>>>(c2l_msg, off_l, src_l, aggr_l, L);
        gemm_bf3<<<gL3, 256>>>(aggr_l, l2l_msg, whi + o_lih, wlo + o_lih,
                               l_bih, gi_l, L, 384, 256, 0, 0);
        gemm_bf3<<<gL3, 256>>>(l_prev, nullptr, whi + o_lhh, wlo + o_lhh,
                               l_bhh, gh_l, L, 384, 128, 0, 0);
        gru_elem<<<(L * D + 255) / 256, 256>>>(gi_l, gh_l, l_prev, l_next, L);
    }
}